// round 1
// baseline (speedup 1.0000x reference)
#include <cuda_runtime.h>

// Problem constants
#define NNODES 4096
#define RREL   16
#define NBASES 8
#define DIN    64
#define DOUT   32
#define KFULL  (RREL * NNODES)          // 65536

// GEMM tiling
#define M_TILE  128
#define KB      32
#define KSPLIT  16
#define KCHUNK  (KFULL / KSPLIT)        // 4096
#define NSTEPS  (KCHUNK / KB)           // 128
#define ASTRIDE 130                     // 128 rows + pad: LDS.64-aligned, conflict-light

#define SMEM_BYTES ((2 * KB * ASTRIDE + 2 * KB * 64) * 4)   // 49664

typedef unsigned long long ull;

// Scratch (no cudaMalloc allowed)
__device__ float g_W[RREL * DIN * DOUT];                    // 128 KB
__device__ float g_FWdup[(size_t)KFULL * 64];               // 16 MB (cols duplicated)
__device__ float g_part[(size_t)KSPLIT * NNODES * DOUT];    // 8 MB

__device__ __forceinline__ void ffma2(ull& d, ull a, ull b) {
    asm("fma.rn.f32x2 %0, %1, %2, %0;" : "+l"(d) : "l"(a), "l"(b));
}

// Stage 1: W[r,i,j] = sum_b comp[r,b] * WF[b,i,j]
__global__ void k_basis(const float* __restrict__ WF, const float* __restrict__ comp) {
    int idx = blockIdx.x * blockDim.x + threadIdx.x;
    if (idx >= RREL * DIN * DOUT) return;
    int r  = idx / (DIN * DOUT);
    int ij = idx % (DIN * DOUT);
    float s = 0.f;
#pragma unroll
    for (int b = 0; b < NBASES; ++b)
        s += comp[r * NBASES + b] * WF[b * (DIN * DOUT) + ij];
    g_W[idx] = s;
}

// Stage 2: FWdup[(r*N+n), 2c..2c+1] = (X @ W_r)[n,c], duplicated per column
__global__ void k_fw(const float* __restrict__ X) {
    __shared__ float Ws[DIN * DOUT];   // 8 KB
    __shared__ float Xs[32 * DIN];     // 8 KB
    const int r = blockIdx.x, nblk = blockIdx.y, t = threadIdx.x;

    for (int i = t; i < DIN * DOUT; i += 256) Ws[i] = g_W[r * DIN * DOUT + i];
    for (int i = t; i < 32 * DIN;  i += 256) Xs[i] = X[(size_t)(nblk * 32) * DIN + i];
    __syncthreads();

    const int row = t >> 3;            // 0..31
    const int c0  = (t & 7) * 4;       // 0,4,...,28
    float a0 = 0.f, a1 = 0.f, a2 = 0.f, a3 = 0.f;
#pragma unroll
    for (int i = 0; i < DIN; ++i) {
        float x = Xs[row * DIN + i];
        float4 w = *(const float4*)&Ws[i * DOUT + c0];
        a0 += x * w.x; a1 += x * w.y; a2 += x * w.z; a3 += x * w.w;
    }
    size_t base = ((size_t)r * NNODES + nblk * 32 + row) * 64 + 2 * c0;
    g_FWdup[base + 0] = a0; g_FWdup[base + 1] = a0;
    g_FWdup[base + 2] = a1; g_FWdup[base + 3] = a1;
    g_FWdup[base + 4] = a2; g_FWdup[base + 5] = a2;
    g_FWdup[base + 6] = a3; g_FWdup[base + 7] = a3;
}

// Stage 3: split-K GEMM partials. part[split] += A[:, chunk] @ FW[chunk, :]
__global__ __launch_bounds__(256, 2) void k_gemm(const float* __restrict__ A) {
    extern __shared__ float smem[];
    float* As = smem;                         // 2 * KB * ASTRIDE, transposed [k][row]
    float* Bs = smem + 2 * KB * ASTRIDE;      // 2 * KB * 64, duplicated cols

    const int t = threadIdx.x;
    const int m0  = blockIdx.x * M_TILE;
    const int kb0 = blockIdx.y * KCHUNK;

    const int arow = t >> 3;                  // 0..31
    const int akk  = (t & 7) << 2;            // 0,4,...,28

    const float4* Ap = (const float4*)A;
    const float4* Bp = (const float4*)g_FWdup;

    float4 ra[4], rb[2];

    // prologue: fetch tile 0
#pragma unroll
    for (int q = 0; q < 4; ++q) {
        size_t off = ((size_t)(m0 + q * 32 + arow) * KFULL + kb0 + akk) >> 2;
        ra[q] = Ap[off];
    }
#pragma unroll
    for (int q = 0; q < 2; ++q)
        rb[q] = Bp[(size_t)kb0 * 16 + q * 256 + t];

    // store tile 0 into buffer 0 (A transposed)
    {
        float* dA = As;
#pragma unroll
        for (int q = 0; q < 4; ++q) {
            int row = q * 32 + arow;
            dA[(akk + 0) * ASTRIDE + row] = ra[q].x;
            dA[(akk + 1) * ASTRIDE + row] = ra[q].y;
            dA[(akk + 2) * ASTRIDE + row] = ra[q].z;
            dA[(akk + 3) * ASTRIDE + row] = ra[q].w;
        }
        float4* dB = (float4*)Bs;
        dB[t]       = rb[0];
        dB[256 + t] = rb[1];
    }
    __syncthreads();

    const int r0 = (t >> 3) * 4;              // row base (even -> LDS.64 aligned)
    const int c0 = (t & 7) * 4;               // col base

    ull acc[8];
#pragma unroll
    for (int i = 0; i < 8; ++i) acc[i] = 0ull;

    for (int step = 0; step < NSTEPS; ++step) {
        const int buf = step & 1;

        if (step + 1 < NSTEPS) {
            const int kb = kb0 + (step + 1) * KB;
#pragma unroll
            for (int q = 0; q < 4; ++q) {
                size_t off = ((size_t)(m0 + q * 32 + arow) * KFULL + kb + akk) >> 2;
                ra[q] = Ap[off];
            }
#pragma unroll
            for (int q = 0; q < 2; ++q)
                rb[q] = Bp[(size_t)kb * 16 + q * 256 + t];
        }

        const float* as = As + buf * (KB * ASTRIDE);
        const float* bs = Bs + buf * (KB * 64);
#pragma unroll
        for (int k = 0; k < KB; ++k) {
            ull a0 = *(const ull*)(as + k * ASTRIDE + r0);
            ull a1 = *(const ull*)(as + k * ASTRIDE + r0 + 2);
            ull b0 = *(const ull*)(bs + k * 64 + 2 * c0);
            ull b1 = *(const ull*)(bs + k * 64 + 2 * c0 + 2);
            ull b2 = *(const ull*)(bs + k * 64 + 2 * c0 + 4);
            ull b3 = *(const ull*)(bs + k * 64 + 2 * c0 + 6);
            ffma2(acc[0], a0, b0);
            ffma2(acc[1], a0, b1);
            ffma2(acc[2], a0, b2);
            ffma2(acc[3], a0, b3);
            ffma2(acc[4], a1, b0);
            ffma2(acc[5], a1, b1);
            ffma2(acc[6], a1, b2);
            ffma2(acc[7], a1, b3);
        }

        if (step + 1 < NSTEPS) {
            const int nbuf = buf ^ 1;
            float* dA = As + nbuf * (KB * ASTRIDE);
#pragma unroll
            for (int q = 0; q < 4; ++q) {
                int row = q * 32 + arow;
                dA[(akk + 0) * ASTRIDE + row] = ra[q].x;
                dA[(akk + 1) * ASTRIDE + row] = ra[q].y;
                dA[(akk + 2) * ASTRIDE + row] = ra[q].z;
                dA[(akk + 3) * ASTRIDE + row] = ra[q].w;
            }
            float4* dB = (float4*)(Bs + nbuf * (KB * 64));
            dB[t]       = rb[0];
            dB[256 + t] = rb[1];
        }
        __syncthreads();
    }

    // epilogue: write partials (acc pairs span rows (r0+2p, r0+2p+1), col c0+j)
    float* pout = g_part + ((size_t)blockIdx.y * NNODES + m0) * DOUT;
#pragma unroll
    for (int p = 0; p < 2; ++p) {
#pragma unroll
        for (int j = 0; j < 4; ++j) {
            float2 v = *(float2*)&acc[p * 4 + j];
            int r = r0 + 2 * p;
            pout[(size_t)r * DOUT + c0 + j]       = v.x;
            pout[(size_t)(r + 1) * DOUT + c0 + j] = v.y;
        }
    }
}

// Stage 4: deterministic split-K reduction
__global__ void k_reduce(float* __restrict__ out) {
    int i = blockIdx.x * blockDim.x + threadIdx.x;   // over 32768 float4s
    const float4* p = (const float4*)g_part;
    float4 s = p[i];
#pragma unroll
    for (int sdx = 1; sdx < KSPLIT; ++sdx) {
        float4 v = p[(size_t)sdx * (NNODES * DOUT / 4) + i];
        s.x += v.x; s.y += v.y; s.z += v.z; s.w += v.w;
    }
    ((float4*)out)[i] = s;
}

extern "C" void kernel_launch(void* const* d_in, const int* in_sizes, int n_in,
                              void* d_out, int out_size) {
    const float* X    = (const float*)d_in[0];   // [4096, 64]
    const float* A    = (const float*)d_in[1];   // [4096, 65536]
    const float* WF   = (const float*)d_in[2];   // [8, 64, 32]
    const float* comp = (const float*)d_in[3];   // [16, 8]
    float* out = (float*)d_out;                  // [4096, 32]

    // >48KB dynamic smem opt-in (process-persistent; harmless to repeat)
    cudaFuncSetAttribute((const void*)k_gemm,
                         cudaFuncAttributeMaxDynamicSharedMemorySize, SMEM_BYTES);

    k_basis<<<(RREL * DIN * DOUT + 255) / 256, 256>>>(WF, comp);
    k_fw<<<dim3(RREL, NNODES / 32), 256>>>(X);
    k_gemm<<<dim3(NNODES / M_TILE, KSPLIT), 256, SMEM_BYTES>>>(A);
    k_reduce<<<(NNODES * DOUT / 4) / 256, 256>>>(out);
}

// round 2
// speedup vs baseline: 2.9221x; 2.9221x over previous
#include <cuda_runtime.h>

#define NNODES 4096
#define RREL   16
#define NBASES 8
#define DIN    64
#define DOUT   32
#define KFULL  (RREL * NNODES)          // 65536

#define M_TILE  128
#define KB      16                      // k per step
#define KH      (KB / 2)                // k-half pairs per step
#define SP      20                      // smem floats per A row (16 + pad, 16B-aligned)
#define KSPLIT  64
#define KCHUNK  (KFULL / KSPLIT)        // 1024
#define NSTEPS  (KCHUNK / KB)           // 64

typedef unsigned long long ull;

// Scratch (no cudaMalloc allowed)
__device__ float g_W[RREL * DIN * DOUT];
__device__ __align__(16) float g_FWp[(size_t)KFULL * DOUT];            // 8 MB, k-pair interleaved
__device__ __align__(16) float g_part[(size_t)KSPLIT * NNODES * DOUT]; // 32 MB

__device__ __forceinline__ void ffma2(ull& d, ull a, ull b) {
    asm("fma.rn.f32x2 %0, %1, %2, %0;" : "+l"(d) : "l"(a), "l"(b));
}
__device__ __forceinline__ void cp_async16(void* smem_dst, const void* gsrc) {
    unsigned s = (unsigned)__cvta_generic_to_shared(smem_dst);
    asm volatile("cp.async.cg.shared.global [%0], [%1], 16;" :: "r"(s), "l"(gsrc));
}

// Stage 1: W[r,i,j] = sum_b comp[r,b] * WF[b,i,j]
__global__ void k_basis(const float* __restrict__ WF, const float* __restrict__ comp) {
    int idx = blockIdx.x * blockDim.x + threadIdx.x;
    if (idx >= RREL * DIN * DOUT) return;
    int r  = idx / (DIN * DOUT);
    int ij = idx % (DIN * DOUT);
    float s = 0.f;
#pragma unroll
    for (int b = 0; b < NBASES; ++b)
        s += comp[r * NBASES + b] * WF[b * (DIN * DOUT) + ij];
    g_W[idx] = s;
}

// Stage 2: FWp[(k>>1)*64 + 2c + (k&1)] = (X @ W_r)[n,c],  k = r*N + n
__global__ void k_fw(const float* __restrict__ X) {
    __shared__ float Ws[DIN * DOUT];
    __shared__ float Xs[32 * DIN];
    const int r = blockIdx.x, nblk = blockIdx.y, t = threadIdx.x;

    for (int i = t; i < DIN * DOUT; i += 256) Ws[i] = g_W[r * DIN * DOUT + i];
    for (int i = t; i < 32 * DIN;  i += 256) Xs[i] = X[(size_t)(nblk * 32) * DIN + i];
    __syncthreads();

    const int row = t >> 3;            // 0..31
    const int c0  = (t & 7) * 4;       // 0,4,...,28
    float a0 = 0.f, a1 = 0.f, a2 = 0.f, a3 = 0.f;
#pragma unroll
    for (int i = 0; i < DIN; ++i) {
        float x = Xs[row * DIN + i];
        float4 w = *(const float4*)&Ws[i * DOUT + c0];
        a0 += x * w.x; a1 += x * w.y; a2 += x * w.z; a3 += x * w.w;
    }
    int k = r * NNODES + nblk * 32 + row;
    size_t base = (size_t)(k >> 1) * (2 * DOUT) + (k & 1);
    g_FWp[base + 2 * (c0 + 0)] = a0;
    g_FWp[base + 2 * (c0 + 1)] = a1;
    g_FWp[base + 2 * (c0 + 2)] = a2;
    g_FWp[base + 2 * (c0 + 3)] = a3;
}

// Stage 3: split-K GEMM, FFMA2 over even/odd-k pairs, A row-major via cp.async
__global__ __launch_bounds__(128) void k_gemm(const float* __restrict__ A) {
    __shared__ float As[2][M_TILE * SP];   // 2 x 10240 B
    __shared__ float Bs[2][KH * 2 * DOUT]; // 2 x 2048 B

    const int t   = threadIdx.x;
    const int m0  = blockIdx.x * M_TILE;
    const int kb0 = blockIdx.y * KCHUNK;

    const int rg = t >> 3;          // row base 0..15 (rows rg + 16j)
    const int c0 = (t & 7) * 4;     // col base

    // async fetch of one step's tiles into buffer `buf`
    auto issue = [&](int buf, int step) {
        const int kb = kb0 + step * KB;
#pragma unroll
        for (int q = 0; q < 4; ++q) {
            int idx = t + 128 * q;       // 0..511
            int row = idx >> 2;
            int k4  = idx & 3;
            cp_async16(&As[buf][row * SP + k4 * 4],
                       A + (size_t)(m0 + row) * KFULL + kb + k4 * 4);
        }
        cp_async16(&Bs[buf][t * 4], g_FWp + (size_t)kb * DOUT + t * 4);
        asm volatile("cp.async.commit_group;");
    };

    issue(0, 0);

    ull acc[8][4];
#pragma unroll
    for (int j = 0; j < 8; ++j)
#pragma unroll
        for (int c = 0; c < 4; ++c) acc[j][c] = 0ull;

    for (int step = 0; step < NSTEPS; ++step) {
        const int buf = step & 1;
        if (step + 1 < NSTEPS) {
            issue(buf ^ 1, step + 1);
            asm volatile("cp.async.wait_group 1;");
        } else {
            asm volatile("cp.async.wait_group 0;");
        }
        __syncthreads();

        const float* as = As[buf];
        const float* bs = Bs[buf];
#pragma unroll
        for (int kh = 0; kh < KH; ++kh) {
            const ull* bp = (const ull*)(bs + kh * (2 * DOUT) + 2 * c0);
            ull b0 = bp[0], b1 = bp[1], b2 = bp[2], b3 = bp[3];
#pragma unroll
            for (int j = 0; j < 8; ++j) {
                ull a = *(const ull*)(as + (rg + 16 * j) * SP + 2 * kh);
                ffma2(acc[j][0], a, b0);
                ffma2(acc[j][1], a, b1);
                ffma2(acc[j][2], a, b2);
                ffma2(acc[j][3], a, b3);
            }
        }
        __syncthreads();
    }

    // epilogue: fold even/odd halves, write partials
    float* pout = g_part + ((size_t)blockIdx.y * NNODES + m0) * DOUT;
#pragma unroll
    for (int j = 0; j < 8; ++j) {
        float4 v;
        float2 f0 = *(float2*)&acc[j][0];
        float2 f1 = *(float2*)&acc[j][1];
        float2 f2 = *(float2*)&acc[j][2];
        float2 f3 = *(float2*)&acc[j][3];
        v.x = f0.x + f0.y; v.y = f1.x + f1.y;
        v.z = f2.x + f2.y; v.w = f3.x + f3.y;
        int r = rg + 16 * j;
        *(float4*)&pout[(size_t)r * DOUT + c0] = v;
    }
}

// Stage 4: deterministic split-K reduction
__global__ void k_reduce(float* __restrict__ out) {
    int i = blockIdx.x * blockDim.x + threadIdx.x;   // over 32768 float4s
    const float4* p = (const float4*)g_part;
    float4 s = p[i];
#pragma unroll
    for (int sdx = 1; sdx < KSPLIT; ++sdx) {
        float4 v = p[(size_t)sdx * (NNODES * DOUT / 4) + i];
        s.x += v.x; s.y += v.y; s.z += v.z; s.w += v.w;
    }
    ((float4*)out)[i] = s;
}

extern "C" void kernel_launch(void* const* d_in, const int* in_sizes, int n_in,
                              void* d_out, int out_size) {
    const float* X    = (const float*)d_in[0];   // [4096, 64]
    const float* A    = (const float*)d_in[1];   // [4096, 65536]
    const float* WF   = (const float*)d_in[2];   // [8, 64, 32]
    const float* comp = (const float*)d_in[3];   // [16, 8]
    float* out = (float*)d_out;                  // [4096, 32]

    k_basis<<<(RREL * DIN * DOUT + 255) / 256, 256>>>(WF, comp);
    k_fw<<<dim3(RREL, NNODES / 32), 256>>>(X);
    k_gemm<<<dim3(NNODES / M_TILE, KSPLIT), 128>>>(A);
    k_reduce<<<(NNODES * DOUT / 4) / 256, 256>>>(out);
}

// round 4
// speedup vs baseline: 4.7371x; 1.6212x over previous
#include <cuda_runtime.h>
#include <cuda_bf16.h>
#include <cstdint>

#define NNODES 4096
#define RREL   16
#define NBASES 8
#define DIN    64
#define DOUT   32
#define KFULL  (RREL * NNODES)          // 65536

#define M_TILE 128
#define KT     64                       // k per step (4 mma k-tiles of 16)
#define KSPLIT 32
#define KCHUNK (KFULL / KSPLIT)         // 2048
#define NSTEPS (KCHUNK / KT)            // 32
#define BP     144                      // B smem row pitch in bytes (72 bf16)

__device__ float g_W[RREL * DIN * DOUT];
__device__ __nv_bfloat16 g_Bh[(size_t)DOUT * KFULL];     // [c][k], 4 MB
__device__ __nv_bfloat16 g_Bl[(size_t)DOUT * KFULL];     // 4 MB
__device__ float g_part[(size_t)KSPLIT * NNODES * DOUT]; // 16 MB

__device__ __forceinline__ void mma16816(float* d, const uint32_t* a,
                                         uint32_t b0, uint32_t b1) {
    asm volatile(
        "mma.sync.aligned.m16n8k16.row.col.f32.bf16.bf16.f32 "
        "{%0,%1,%2,%3}, {%4,%5,%6,%7}, {%8,%9}, {%0,%1,%2,%3};"
        : "+f"(d[0]), "+f"(d[1]), "+f"(d[2]), "+f"(d[3])
        : "r"(a[0]), "r"(a[1]), "r"(a[2]), "r"(a[3]), "r"(b0), "r"(b1));
}

// Stage 1: W[r,i,j] = sum_b comp[r,b] * WF[b,i,j]
__global__ void k_basis(const float* __restrict__ WF, const float* __restrict__ comp) {
    int idx = blockIdx.x * blockDim.x + threadIdx.x;
    if (idx >= RREL * DIN * DOUT) return;
    int r = idx / (DIN * DOUT), ij = idx % (DIN * DOUT);
    float s = 0.f;
#pragma unroll
    for (int b = 0; b < NBASES; ++b)
        s += comp[r * NBASES + b] * WF[b * (DIN * DOUT) + ij];
    g_W[idx] = s;
}

// Stage 2: FW = X @ W_r, split into bf16 hi/lo, stored transposed [c][k]
__global__ void k_fw(const float* __restrict__ X) {
    __shared__ float Ws[DIN * DOUT];
    __shared__ float Xs[32 * DIN];
    const int r = blockIdx.x, nblk = blockIdx.y, t = threadIdx.x;

    for (int i = t; i < DIN * DOUT; i += 256) Ws[i] = g_W[r * DIN * DOUT + i];
    for (int i = t; i < 32 * DIN;  i += 256) Xs[i] = X[(size_t)(nblk * 32) * DIN + i];
    __syncthreads();

    const int row = t >> 3;
    const int c0  = (t & 7) * 4;
    float a[4] = {0.f, 0.f, 0.f, 0.f};
#pragma unroll
    for (int i = 0; i < DIN; ++i) {
        float x = Xs[row * DIN + i];
        float4 w = *(const float4*)&Ws[i * DOUT + c0];
        a[0] += x * w.x; a[1] += x * w.y; a[2] += x * w.z; a[3] += x * w.w;
    }
    int k = r * NNODES + nblk * 32 + row;
#pragma unroll
    for (int i = 0; i < 4; ++i) {
        __nv_bfloat16 h = __float2bfloat16(a[i]);
        __nv_bfloat16 l = __float2bfloat16(a[i] - __bfloat162float(h));
        g_Bh[(size_t)(c0 + i) * KFULL + k] = h;
        g_Bl[(size_t)(c0 + i) * KFULL + k] = l;
    }
}

// Stage 3: split-K GEMM on mma.sync bf16 with in-register fp32->bf16 split of A
__global__ __launch_bounds__(256, 2) void k_gemm(const float* __restrict__ A) {
    __shared__ __align__(16) char Bsm[2][2][32 * BP];   // [buf][h/l], 18.4 KB

    const int t    = threadIdx.x;
    const int wid  = t >> 5, lane = t & 31;
    const int r4   = lane >> 2;          // 0..7
    const int kq   = (lane & 3) * 2;     // 0,2,4,6
    const int m0   = blockIdx.x * M_TILE;
    const size_t kb0 = (size_t)blockIdx.y * KCHUNK;

    const float* Abase = A + (size_t)(m0 + wid * 16 + r4) * KFULL + kb0 + kq;
    const int brow = t >> 3, bc16 = t & 7;
    const __nv_bfloat16* BhB = g_Bh + (size_t)brow * KFULL + kb0 + bc16 * 8;
    const __nv_bfloat16* BlB = g_Bl + (size_t)brow * KFULL + kb0 + bc16 * 8;
    const int bsts = brow * BP + bc16 * 16;

    float2 af[4][4];
#pragma unroll
    for (int kt = 0; kt < 4; ++kt) {
        const float* p = Abase + kt * 16;
        af[kt][0] = *(const float2*)p;
        af[kt][1] = *(const float2*)(p + 8 * (size_t)KFULL);
        af[kt][2] = *(const float2*)(p + 8);
        af[kt][3] = *(const float2*)(p + 8 * (size_t)KFULL + 8);
    }
    {
        uint4 vh = *(const uint4*)BhB;
        uint4 vl = *(const uint4*)BlB;
        *(uint4*)&Bsm[0][0][bsts] = vh;
        *(uint4*)&Bsm[0][1][bsts] = vl;
    }
    __syncthreads();

    float d[4][4] = {};

    for (int step = 0; step < NSTEPS; ++step) {
        const int buf = step & 1;

        float2 nf[4][4];
        uint4 vh, vl;
        if (step + 1 < NSTEPS) {
#pragma unroll
            for (int kt = 0; kt < 4; ++kt) {
                const float* p = Abase + (step + 1) * KT + kt * 16;
                nf[kt][0] = *(const float2*)p;
                nf[kt][1] = *(const float2*)(p + 8 * (size_t)KFULL);
                nf[kt][2] = *(const float2*)(p + 8);
                nf[kt][3] = *(const float2*)(p + 8 * (size_t)KFULL + 8);
            }
            vh = *(const uint4*)(BhB + (step + 1) * KT);
            vl = *(const uint4*)(BlB + (step + 1) * KT);
        }

#pragma unroll
        for (int kt = 0; kt < 4; ++kt) {
            uint32_t ah[4], al[4];
#pragma unroll
            for (int j = 0; j < 4; ++j) {
                float fx = af[kt][j].x, fy = af[kt][j].y;
                uint32_t h;
                asm("cvt.rn.bf16x2.f32 %0, %1, %2;" : "=r"(h) : "f"(fy), "f"(fx));
                float hx = __uint_as_float(h << 16);
                float hy = __uint_as_float(h & 0xffff0000u);
                uint32_t l;
                asm("cvt.rn.bf16x2.f32 %0, %1, %2;" : "=r"(l) : "f"(fy - hy), "f"(fx - hx));
                ah[j] = h; al[j] = l;
            }
#pragma unroll
            for (int n = 0; n < 4; ++n) {
                const char* ph = &Bsm[buf][0][(n * 8 + r4) * BP + (kt * 16 + kq) * 2];
                const char* pl = &Bsm[buf][1][(n * 8 + r4) * BP + (kt * 16 + kq) * 2];
                uint32_t bh0 = *(const uint32_t*)ph;
                uint32_t bh1 = *(const uint32_t*)(ph + 16);
                uint32_t bl0 = *(const uint32_t*)pl;
                uint32_t bl1 = *(const uint32_t*)(pl + 16);
                mma16816(d[n], ah, bh0, bh1);
                mma16816(d[n], ah, bl0, bl1);
                mma16816(d[n], al, bh0, bh1);
            }
        }

        if (step + 1 < NSTEPS) {
            *(uint4*)&Bsm[buf ^ 1][0][bsts] = vh;
            *(uint4*)&Bsm[buf ^ 1][1][bsts] = vl;
#pragma unroll
            for (int kt = 0; kt < 4; ++kt)
#pragma unroll
                for (int j = 0; j < 4; ++j)
                    af[kt][j] = nf[kt][j];
        }
        __syncthreads();
    }

    // epilogue: write partials
    float* po = g_part + ((size_t)blockIdx.y * NNODES + m0 + wid * 16 + r4) * DOUT + kq;
#pragma unroll
    for (int n = 0; n < 4; ++n) {
        *(float2*)(po + n * 8)            = make_float2(d[n][0], d[n][1]);
        *(float2*)(po + 8 * DOUT + n * 8) = make_float2(d[n][2], d[n][3]);
    }
}

// Stage 4: deterministic split-K reduction
__global__ void k_reduce(float* __restrict__ out) {
    int i = blockIdx.x * blockDim.x + threadIdx.x;  // over 32768 float4s
    const float4* p = (const float4*)g_part;
    float4 s = p[i];
#pragma unroll
    for (int sdx = 1; sdx < KSPLIT; ++sdx) {
        float4 v = p[(size_t)sdx * (NNODES * DOUT / 4) + i];
        s.x += v.x; s.y += v.y; s.z += v.z; s.w += v.w;
    }
    ((float4*)out)[i] = s;
}

extern "C" void kernel_launch(void* const* d_in, const int* in_sizes, int n_in,
                              void* d_out, int out_size) {
    const float* X    = (const float*)d_in[0];   // [4096, 64]
    const float* A    = (const float*)d_in[1];   // [4096, 65536]
    const float* WF   = (const float*)d_in[2];   // [8, 64, 32]
    const float* comp = (const float*)d_in[3];   // [16, 8]
    float* out = (float*)d_out;                  // [4096, 32]

    k_basis<<<(RREL * DIN * DOUT + 255) / 256, 256>>>(WF, comp);
    k_fw<<<dim3(RREL, NNODES / 32), 256>>>(X);
    k_gemm<<<dim3(NNODES / M_TILE, KSPLIT), 256>>>(A);
    k_reduce<<<(NNODES * DOUT / 4) / 256, 256>>>(out);
}